// round 15
// baseline (speedup 1.0000x reference)
#include <cuda_runtime.h>
#include <cstdint>

#define FSZ   50
#define NPIX  2500
#define OC    512
#define KTOT  4608      // 512*9
#define NANCH 22500     // 2500*9
#define PRE   6000
#define NW    94        // ceil(6000/64)
#define ROWS  6016
#define POST  300
#define PADW  52
#define PADCH 2704      // 52*52

// ---------------- scratch (static device allocations) ----------------
__device__ float               g_wre[OC * KTOT];           // weights, k' = r*512+ch
__device__ float               g_inpad[OC * PADCH + 256];  // padded batch-7 input
__device__ float               g_feat[OC * NPIX];
__device__ float4              g_boxes[NANCH];
__device__ unsigned            g_score[NANCH];
__device__ float               g_hpart[4][54 * NPIX];
__device__ unsigned            g_hist[65536];
__device__ unsigned            g_bsum[256];
__device__ unsigned            g_pref[65536];
__device__ unsigned            g_bfill[65536];
__device__ unsigned long long  g_bkey[NANCH];
__device__ float4              g_sbox[ROWS];
__device__ float               g_area[ROWS];
__device__ unsigned long long  g_maskT[(size_t)NW * ROWS];
__device__ unsigned long long  g_keep[NW];

// packed fp32x2 ops (sm_103a — only reachable via PTX)
#define FMA2(c, a, b) asm("fma.rn.f32x2 %0, %1, %2, %3;" : "=l"(c) : "l"(a), "l"(b), "l"(c))
#define ADD2(c, a, b) asm("add.rn.f32x2 %0, %1, %2;" : "=l"(c) : "l"(a), "l"(b))
__device__ __forceinline__ unsigned long long dup2(float x) {
    unsigned long long d;
    asm("mov.b64 %0, {%1, %1};" : "=l"(d) : "f"(x));
    return d;
}
__device__ __forceinline__ uint32_t smem_u32(const void* p) {
    uint32_t a;
    asm("{ .reg .u64 t; cvta.to.shared.u64 t, %1; cvt.u32.u64 %0, t; }" : "=r"(a) : "l"(p));
    return a;
}
#define CPA16(dst, src) asm volatile("cp.async.cg.shared.global [%0], [%1], 16;" :: "r"(dst), "l"(src))
#define CPA8(dst, src)  asm volatile("cp.async.ca.shared.global [%0], [%1], 8;"  :: "r"(dst), "l"(src))
#define CPA4(dst, src)  asm volatile("cp.async.ca.shared.global [%0], [%1], 4;"  :: "r"(dst), "l"(src))
#define CPCOMMIT()      asm volatile("cp.async.commit_group;" ::: "memory")
#define CPWAIT1()       asm volatile("cp.async.wait_group 1;" ::: "memory")

// ---------------- launch 0: weight transpose (coalesced both sides) + zero hist ----------------
__global__ __launch_bounds__(256) void prep_w_kernel(const float* __restrict__ cw) {
    __shared__ float ws[KTOT / 512 * 512];   // 4608 floats
    int b = blockIdx.x;    // = oc
    int t = threadIdx.x;
    for (int i = t; i < KTOT; i += 256) ws[i] = cw[b * KTOT + i];
    int idx = b * 256 + t;
    if (idx < 65536) g_hist[idx] = 0u;
    else g_bfill[idx - 65536] = 0u;
    __syncthreads();
    for (int k = t; k < KTOT; k += 256) {
        int ch = k & 511, r = k >> 9;
        g_wre[b * KTOT + k] = ws[ch * 9 + r];
    }
}

// ---------------- launch 1: input pad ----------------
__global__ void prep_in_kernel(const float* __restrict__ in7) {
    int j = blockIdx.x * 256 + threadIdx.x;
    if (j >= OC * PADCH) return;
    int c = j / PADCH, rem = j - c * PADCH;
    int y = rem / PADW, x = rem - y * PADW;
    float v = 0.f;
    if (y >= 1 && y <= 50 && x >= 1 && x <= 50)
        v = in7[c * NPIX + (y - 1) * FSZ + (x - 1)];
    g_inpad[j] = v;
}

// ---------------- launch 2: misc setup ----------------
__global__ void setup_misc_kernel() {
    int i = blockIdx.x * 256 + threadIdx.x;
    if (i < ROWS - PRE) {
        g_sbox[PRE + i] = make_float4(0.f, 0.f, 0.f, 0.f);
        g_area[PRE + i] = 1.f;
    }
    if (i < NW) g_keep[i] = 0ull;
}

// ---------------- launch 3: conv 3x3 (batch 7) + leaky relu ----------------
// implicit GEMM 512x2500x4608. CTA = 256 threads = 2 split-K warpgroups x 128.
// CTA tile 128oc x 80px; grid (32,4) = 128 CTAs. Thread tile 8oc x 5 px-pairs
// (40 FFMA2 per kk -> ~75% fma instruction mix). B pairs {2pg,2pg+1,16+2pg,
// 17+2pg,32+pg}: 2x LDS.128 + 1x LDS.64 per kk. A og-groups (8 rows x 80B)
// padded to 656B so the 4 broadcast addresses per warp hit distinct banks.
#define CBK    16
#define NCHK2  144                    // chunks per warpgroup (4608/2/16)
#define A_SZ   10496                  // 16 og-groups * 656B
#define B_OFF  10496
#define STG    15872                  // A 10496 + B 5376
#define WGB    31744                  // 2 stages
#define DSMSZ  63488
extern __shared__ char dsm[];

__global__ __launch_bounds__(256) void conv3_kernel(const float* __restrict__ bias) {
    uint32_t sb = smem_u32(dsm);
    int t = threadIdx.x;
    int wg = t >> 7;                  // 0 / 1
    int wt = t & 127;
    int px0 = blockIdx.x * 80, oc0 = blockIdx.y * 128;
    int og = wt >> 3;                 // 0..15 (8 oc each)
    int pg = wt & 7;                  // 0..7
    int wgk0 = wg * 2304;             // k-range start
    uint32_t wgbase = sb + wg * WGB;

    // pair indices handled by this thread
    int prs[5] = {2 * pg, 2 * pg + 1, 16 + 2 * pg, 17 + 2 * pg, 32 + pg};

    // A staging: 4 x 16B granules per thread (128oc x 4ks = 512 granules)
    int a_oc[4], a_ks[4];
    const float* a_src[4];
    uint32_t a_so[4];
#pragma unroll
    for (int s = 0; s < 4; s++) {
        int idx = wt + 128 * s;
        a_oc[s] = idx >> 2; a_ks[s] = idx & 3;
        a_src[s] = g_wre + (size_t)(oc0 + a_oc[s]) * KTOT + a_ks[s] * 4 + wgk0;
        a_so[s] = (a_oc[s] >> 3) * 656 + (a_oc[s] & 7) * 80 + a_ks[s] * 16;
    }

    // B staging: 10 x 4B per thread (1280 granules = 16kk x 80px, linear c*4)
    int b_kk[10], b_pix[10];
    uint32_t b_so[10];
#pragma unroll
    for (int s = 0; s < 10; s++) {
        int g = wt + 128 * s;
        int kk = g / 80, c = g - 80 * kk;
        int p = px0 + c;
        int py = p / 50, px = p - 50 * py;
        b_kk[s] = kk;
        b_pix[s] = py * PADW + px;
        b_so[s] = B_OFF + kk * 336 + c * 4;
    }

    unsigned long long acc[8][5];
#pragma unroll
    for (int i = 0; i < 8; i++)
#pragma unroll
        for (int j = 0; j < 5; j++) acc[i][j] = 0ull;

    auto issue = [&](int q, int st) {
        int kb = wgk0 + q * CBK;
        int r = kb >> 9, ch0 = kb & 511;
        int ry = r / 3;
        const float* ib = g_inpad + (size_t)ch0 * PADCH + ry * PADW + (r - 3 * ry);
        uint32_t sbase = wgbase + st * STG;
#pragma unroll
        for (int s = 0; s < 4; s++)
            CPA16(sbase + a_so[s], a_src[s] + q * CBK);
#pragma unroll
        for (int s = 0; s < 10; s++)
            CPA4(sbase + b_so[s], ib + (size_t)b_kk[s] * PADCH + b_pix[s]);
    };

    issue(0, 0); CPCOMMIT();
    issue(1, 1); CPCOMMIT();

    int barid = wg + 1;
    for (int q = 0; q < NCHK2; q++) {
        int st = q & 1;
        CPWAIT1();
        asm volatile("bar.sync %0, 128;" :: "r"(barid) : "memory");
        const char* A_ = dsm + wg * WGB + st * STG + og * 656;
        const char* B_ = dsm + wg * WGB + st * STG + B_OFF;

        // b2 double buffer: preload kk=0 (2x LDS.128 + 1x LDS.64)
        unsigned long long b2c[5], b2n[5];
        {
            ulonglong2 u0 = *(const ulonglong2*)(B_ + pg * 16);
            ulonglong2 u1 = *(const ulonglong2*)(B_ + 128 + pg * 16);
            b2c[0] = u0.x; b2c[1] = u0.y;
            b2c[2] = u1.x; b2c[3] = u1.y;
            b2c[4] = *(const unsigned long long*)(B_ + 256 + pg * 8);
        }

#pragma unroll
        for (int kk4 = 0; kk4 < CBK; kk4 += 4) {
            float4 av[8];
#pragma unroll
            for (int i = 0; i < 8; i++)
                av[i] = *(const float4*)(A_ + i * 80 + kk4 * 4);
#pragma unroll
            for (int kk = 0; kk < 4; kk++) {
                int gk = kk4 + kk;
                if (gk < CBK - 1) {
                    const char* brow = B_ + (gk + 1) * 336;
                    ulonglong2 u0 = *(const ulonglong2*)(brow + pg * 16);
                    ulonglong2 u1 = *(const ulonglong2*)(brow + 128 + pg * 16);
                    b2n[0] = u0.x; b2n[1] = u0.y;
                    b2n[2] = u1.x; b2n[3] = u1.y;
                    b2n[4] = *(const unsigned long long*)(brow + 256 + pg * 8);
                }
#pragma unroll
                for (int i = 0; i < 8; i++) {
                    float afv = (kk == 0) ? av[i].x : (kk == 1) ? av[i].y
                              : (kk == 2) ? av[i].z : av[i].w;
                    unsigned long long da = dup2(afv);
#pragma unroll
                    for (int j = 0; j < 5; j++)
                        FMA2(acc[i][j], da, b2c[j]);
                }
                if (gk < CBK - 1) {
#pragma unroll
                    for (int j = 0; j < 5; j++) b2c[j] = b2n[j];
                }
            }
        }
        // issue next-next chunk into the stage just freed
        asm volatile("bar.sync %0, 128;" :: "r"(barid) : "memory");
        if (q + 2 < NCHK2) issue(q + 2, st);
        CPCOMMIT();
    }

    // combine split-K halves (reuse stage smem), wg0 finishes
    __syncthreads();
    unsigned long long* epi = (unsigned long long*)dsm;
    if (wg == 1) {
#pragma unroll
        for (int i = 0; i < 8; i++)
#pragma unroll
            for (int j = 0; j < 5; j++) epi[wt * 41 + i * 5 + j] = acc[i][j];
    }
    __syncthreads();
    if (wg == 0) {
#pragma unroll
        for (int i = 0; i < 8; i++) {
            int oc = oc0 + og * 8 + i;
            float bv = bias[oc];
#pragma unroll
            for (int j = 0; j < 5; j++) {
                ADD2(acc[i][j], acc[i][j], epi[wt * 41 + i * 5 + j]);
                int p = px0 + 2 * prs[j];
                if (p < NPIX) {   // NPIX even -> pair-granular validity
                    float lo, hi;
                    asm("mov.b64 {%0, %1}, %2;" : "=f"(lo), "=f"(hi) : "l"(acc[i][j]));
                    lo += bv; hi += bv;
                    lo = (lo >= 0.f) ? lo : 0.01f * lo;
                    hi = (hi >= 0.f) ? hi : 0.01f * hi;
                    *(float2*)&g_feat[(size_t)oc * NPIX + p] = make_float2(lo, hi);
                }
            }
        }
    }
}

// ---------------- heads part 1: 1x1 convs, 4 channel-group partials ----------------
// grid (37, 4): 148 blocks (one per SM), 68 px per block.
__global__ __launch_bounds__(128) void heads_part_kernel(const float* __restrict__ reg_w,
                                                         const float* __restrict__ cls_w) {
    __shared__ float wsm[128][56];
    int t = threadIdx.x;
    int cg = blockIdx.y;
    int c0 = cg * 128;
    int p = blockIdx.x * 68 + t;
    bool act = (t < 68) && (p < NPIX);

    for (int i = t; i < 54 * 128; i += 128) {
        int o = i / 128, c = i - o * 128;
        float v = (o < 36) ? reg_w[o * 512 + c0 + c] : cls_w[(o - 36) * 512 + c0 + c];
        wsm[c][o] = v;
    }
    __syncthreads();

    float acc[54];
#pragma unroll
    for (int o = 0; o < 54; o++) acc[o] = 0.f;
    if (act) {
        for (int c = 0; c < 128; c++) {
            float f = g_feat[(size_t)(c0 + c) * NPIX + p];
#pragma unroll
            for (int o = 0; o < 54; o++) acc[o] += f * wsm[c][o];
        }
#pragma unroll
        for (int o = 0; o < 54; o++)
            g_hpart[cg][o * NPIX + p] = acc[o];
    }
}

// ---------------- heads part 2: combine + softmax + decode + scores + histogram ----------------
__global__ __launch_bounds__(128) void heads_fin_kernel(const float* __restrict__ reg_b,
                                                        const float* __restrict__ cls_b) {
    int p = blockIdx.x * 128 + threadIdx.x;
    if (p >= NPIX) return;
    float acc[54];
#pragma unroll
    for (int o = 0; o < 54; o++)
        acc[o] = (g_hpart[0][o * NPIX + p] + g_hpart[1][o * NPIX + p]) +
                 (g_hpart[2][o * NPIX + p] + g_hpart[3][o * NPIX + p]);
#pragma unroll
    for (int o = 0; o < 36; o++) acc[o] += reg_b[o];
#pragma unroll
    for (int o = 0; o < 18; o++) acc[36 + o] += cls_b[o];

    int pq = p / FSZ, pr = p - pq * FSZ;
    float cxv = 16.f * (float)pq + 8.f;
    float cyv = 16.f * (float)pr + 8.f;
    const float ssv[3]  = {8.f, 16.f, 32.f};
    const float sqr[3]  = {0.70710678f, 1.0f, 1.41421356f};
    const float sqi[3]  = {1.41421356f, 1.0f, 0.70710678f};
    const float NEGINF = __int_as_float(0xff800000);

#pragma unroll
    for (int k = 0; k < 9; k++) {
        float pr0 = acc[k * 4 + 0], pr1 = acc[k * 4 + 1];
        float pr2 = acc[k * 4 + 2], pr3 = acc[k * 4 + 3];
        float l0 = acc[36 + k * 2], l1 = acc[36 + k * 2 + 1];
        float m  = fmaxf(l0, l1);
        float e0 = expf(l0 - m), e1 = expf(l1 - m);
        float sc = e1 / (e0 + e1);

        int ri = k / 3, si = k - 3 * ri;
        float hk = (16.f * ssv[si]) * sqr[ri];
        float wk = (16.f * ssv[si]) * sqi[ri];
        float ax1 = cxv - wk * 0.5f;
        float ay1 = cyv - hk * 0.5f;
        const float hi = 799.f;
        float rx1 = fminf(fmaxf(pr0 + ax1, 0.f), hi);
        float ry1 = fminf(fmaxf(pr1 + ay1, 0.f), hi);
        float rx2 = fminf(fmaxf(((pr0 + ax1) + pr2) + wk, 0.f), hi);
        float ry2 = fminf(fmaxf(((pr1 + ay1) + pr3) + hk, 0.f), hi);
        float wv = pr2 + wk, hv = pr3 + hk;
        bool valid = (wv >= 16.f) && (hv >= 16.f);
        float s = valid ? sc : NEGINF;

        int a = p * 9 + k;
        g_boxes[a] = make_float4(rx1, ry1, rx2, ry2);
        unsigned u = __float_as_uint(s);
        u = (u >> 31) ? ~u : (u | 0x80000000u);
        g_score[a] = u;
        atomicAdd(&g_hist[u >> 16], 1u);
    }
}

// ---------------- bucket sums (coalesced) ----------------
__global__ __launch_bounds__(256) void bucket_sum_kernel() {
    __shared__ unsigned sh[256];
    int b = blockIdx.x, t = threadIdx.x;
    sh[t] = g_hist[b * 256 + t];
    __syncthreads();
    for (int off = 128; off; off >>= 1) {
        if (t < off) sh[t] += sh[t + off];
        __syncthreads();
    }
    if (t == 0) g_bsum[b] = sh[0];
}

// ---------------- suffix-prefix per bucket (coalesced) ----------------
__global__ __launch_bounds__(256) void bucket_pref_kernel() {
    __shared__ unsigned sh[256];
    __shared__ unsigned above_s;
    int b = blockIdx.x, t = threadIdx.x;
    unsigned v = (t > b) ? g_bsum[t] : 0u;
    sh[t] = v;
    __syncthreads();
    for (int off = 128; off; off >>= 1) {
        if (t < off) sh[t] += sh[t + off];
        __syncthreads();
    }
    if (t == 0) above_s = sh[0];
    __syncthreads();
    unsigned above = above_s;
    unsigned h = g_hist[b * 256 + t];
    __syncthreads();
    sh[t] = h;
    __syncthreads();
    for (int off = 1; off < 256; off <<= 1) {
        unsigned x = (t + off < 256) ? sh[t + off] : 0u;
        __syncthreads();
        sh[t] += x;
        __syncthreads();
    }
    g_pref[b * 256 + t] = above + sh[t] - h;   // count strictly higher
}

// ---------------- bucket fill (only buckets that can reach top-6000) ----------------
__global__ void bucket_fill_kernel() {
    int i = blockIdx.x * 256 + threadIdx.x;
    if (i >= NANCH) return;
    unsigned s = g_score[i];
    unsigned b = s >> 16;
    unsigned base = g_pref[b];
    if (base >= PRE) return;
    unsigned slot = atomicAdd(&g_bfill[b], 1u);
    g_bkey[base + slot] = ((unsigned long long)s << 32) | (unsigned)(~i);
}

// ---------------- exact rank + scatter ----------------
__global__ void rank_scatter_kernel() {
    int i = blockIdx.x * 256 + threadIdx.x;
    if (i >= NANCH) return;
    unsigned s = g_score[i];
    unsigned b = s >> 16;
    unsigned base = g_pref[b];
    if (base >= PRE) return;
    unsigned cnt = g_hist[b];
    unsigned long long my = ((unsigned long long)s << 32) | (unsigned)(~i);
    unsigned r = base;
    for (unsigned q = 0; q < cnt; q++)
        r += (g_bkey[base + q] > my);
    if (r < PRE) {
        float4 bx = g_boxes[i];
        g_sbox[r] = bx;
        g_area[r] = (bx.z - bx.x + 1.f) * (bx.w - bx.y + 1.f);
    }
}

// ---------------- NMS mask, transposed layout (yy2 = max bug preserved) ----------------
// division-free: ov > 0.7  <=>  (den>0 && inter > 0.7*den) || (den==0 && inter>0)
// 256 threads cover 4 j-tiles per block; grid (24, 94), early-out below diagonal.
__global__ __launch_bounds__(256) void nms_mask_kernel() {
    int gi = blockIdx.y;
    int jb = blockIdx.x * 4;
    if (jb + 3 < gi) return;
    __shared__ float4 cbx[4][64];
    __shared__ float  car[4][64];
    int t = threadIdx.x;
    int jt = t >> 6, tt = t & 63;
    int gj = jb + jt;
    if (gj < NW) {
        cbx[jt][tt] = g_sbox[gj * 64 + tt];
        car[jt][tt] = g_area[gj * 64 + tt];
    }
    __syncthreads();
    if (gj < gi || gj >= NW) return;
    int i = gi * 64 + tt;
    float4 bi = g_sbox[i];
    float  ai = g_area[i];
    unsigned long long word = 0;
#pragma unroll 8
    for (int jj = 0; jj < 64; jj++) {
        float4 bj = cbx[jt][jj];
        float xx1 = fmaxf(bi.x, bj.x);
        float yy1 = fmaxf(bi.y, bj.y);
        float xx2 = fminf(bi.z, bj.z);
        float yy2 = fmaxf(bi.w, bj.w);   // reference bug: maximum, not minimum
        float w = fmaxf(0.f, xx2 - xx1 + 1.f);
        float h = fmaxf(0.f, yy2 - yy1 + 1.f);
        float inter = w * h;
        float den = ai + car[jt][jj] - inter;
        bool sup = (den > 0.f) ? (inter > 0.7f * den) : ((den == 0.f) && (inter > 0.f));
        word |= ((unsigned long long)sup) << jj;
    }
    g_maskT[(size_t)gj * ROWS + i] = word;   // coalesced across tt
}

// ---------------- greedy NMS scan: smem-staged blocks, cp.async double-buffered ----------------
// Stage layout: [2 stages][64 rows][95 words] u64 (95 = NW padded, conflict-free).
// Per cb: stage holds mask rows cb*64..cb*64+63 for ALL 94 words, loaded one cb
// ahead. Greedy (thread 0) and OR phase read shared instead of L2.
#define SCAN_STGW 6080              // 64*95 u64 per stage
#define SCAN_SMEM (2 * SCAN_STGW * 8)
__global__ __launch_bounds__(256) void nms_scan_kernel() {
    uint32_t sb = smem_u32(dsm);
    __shared__ unsigned long long s_remv, s_kept;
    int t = threadIdx.x;
    unsigned long long remv = 0;                       // thread t owns word g=t

    auto load = [&](int cb, int st) {
        uint32_t base = sb + st * (SCAN_STGW * 8);
        for (int i = t; i < NW * 64; i += 256) {
            int g = i >> 6, r = i & 63;
            CPA8(base + (uint32_t)(r * 95 + g) * 8,
                 g_maskT + (size_t)g * ROWS + cb * 64 + r);
        }
    };

    load(0, 0); CPCOMMIT();
    for (int cb = 0; cb < NW; cb++) {
        if (t == cb) s_remv = remv;
        if (cb + 1 < NW) load(cb + 1, (cb + 1) & 1);
        CPCOMMIT();
        CPWAIT1();
        __syncthreads();
        const unsigned long long* blk =
            (const unsigned long long*)dsm + (cb & 1) * SCAN_STGW;
        if (t == 0) {
            unsigned long long v = s_remv, kept = 0ull;
            int lim = PRE - cb * 64; if (lim > 64) lim = 64;
            unsigned long long avail = ~v;
            if (lim < 64) avail &= (1ull << lim) - 1ull;
            while (avail) {
                int j = __ffsll((long long)avail) - 1;
                kept |= 1ull << j;
                v |= blk[j * 95 + cb];
                avail &= ~v;
                avail &= (j < 63) ? (~0ull << (j + 1)) : 0ull;
            }
            s_kept = kept;
            g_keep[cb] = kept;
        }
        __syncthreads();
        if (t > cb && t < NW) {
            unsigned long long kk = s_kept;
            const unsigned long long* bp = blk + t;
            while (kk) {
                unsigned long long m[8];
#pragma unroll
                for (int u = 0; u < 8; u++) m[u] = 0ull;
#pragma unroll
                for (int u = 0; u < 8; u++) {
                    if (!kk) break;
                    int j = __ffsll((long long)kk) - 1; kk &= kk - 1;
                    m[u] = bp[j * 95];
                }
                remv |= ((m[0] | m[1]) | (m[2] | m[3])) |
                        ((m[4] | m[5]) | (m[6] | m[7]));
            }
        }
        __syncthreads();   // protect stage reuse + s_remv handoff ordering
    }
}

// ---------------- emit top-300 ----------------
__global__ __launch_bounds__(256) void output_kernel(float* __restrict__ out) {
    __shared__ int cnts[256];
    __shared__ int offs[256];
    __shared__ int Ktot;
    int t = threadIdx.x;
    int lo = t * 24;
    int hi = lo + 24; if (hi > PRE) hi = PRE;
    int c = 0;
    for (int i = lo; i < hi; i++)
        c += (int)((g_keep[i >> 6] >> (i & 63)) & 1ull);
    cnts[t] = c;
    __syncthreads();
    if (t == 0) {
        int r = 0;
        for (int q = 0; q < 256; q++) { offs[q] = r; r += cnts[q]; }
        Ktot = r;
    }
    __syncthreads();
    int K = Ktot;
    int pk = offs[t];
    for (int i = lo; i < hi; i++) {
        bool kept = (g_keep[i >> 6] >> (i & 63)) & 1ull;
        int pos = kept ? pk : (K + (i - pk));
        if (kept) pk++;
        if (pos < POST) {
            float4 b = g_sbox[i];
            out[pos * 4 + 0] = b.x;
            out[pos * 4 + 1] = b.y;
            out[pos * 4 + 2] = b.z - b.x + 1.f;
            out[pos * 4 + 3] = b.w - b.y + 1.f;
        }
    }
}

// ---------------- launch ----------------
extern "C" void kernel_launch(void* const* d_in, const int* in_sizes, int n_in,
                              void* d_out, int out_size) {
    const float* in_features = (const float*)d_in[0];
    const float* conv_w = (const float*)d_in[1];
    const float* conv_b = (const float*)d_in[2];
    const float* reg_w  = (const float*)d_in[3];
    const float* reg_b  = (const float*)d_in[4];
    const float* cls_w  = (const float*)d_in[5];
    const float* cls_b  = (const float*)d_in[6];
    float* out = (float*)d_out;

    // only batch index 7 feeds the output
    const float* in7 = in_features + (size_t)7 * 512 * NPIX;

    cudaFuncSetAttribute(conv3_kernel,
                         cudaFuncAttributeMaxDynamicSharedMemorySize, DSMSZ);
    cudaFuncSetAttribute(nms_scan_kernel,
                         cudaFuncAttributeMaxDynamicSharedMemorySize, SCAN_SMEM);

    prep_w_kernel<<<512, 256>>>(conv_w);                         // 0
    prep_in_kernel<<<(OC * PADCH + 255) / 256, 256>>>(in7);      // 1
    setup_misc_kernel<<<1, 256>>>();                             // 2
    conv3_kernel<<<dim3(32, 4), 256, DSMSZ>>>(conv_b);           // 3 <- profiled
    heads_part_kernel<<<dim3(37, 4), 128>>>(reg_w, cls_w);       // 4
    heads_fin_kernel<<<20, 128>>>(reg_b, cls_b);                 // 5
    bucket_sum_kernel<<<256, 256>>>();                           // 6
    bucket_pref_kernel<<<256, 256>>>();                          // 7
    bucket_fill_kernel<<<88, 256>>>();                           // 8
    rank_scatter_kernel<<<88, 256>>>();                          // 9
    nms_mask_kernel<<<dim3(24, NW), 256>>>();                    // 10
    nms_scan_kernel<<<1, 256, SCAN_SMEM>>>();                    // 11
    output_kernel<<<1, 256>>>(out);                              // 12
}

// round 16
// speedup vs baseline: 1.0761x; 1.0761x over previous
#include <cuda_runtime.h>
#include <cstdint>

#define FSZ   50
#define NPIX  2500
#define OC    512
#define KTOT  4608      // 512*9
#define NANCH 22500     // 2500*9
#define PRE   6000
#define NW    94        // ceil(6000/64)
#define ROWS  6016
#define POST  300
#define PADW  52
#define PADCH 2704      // 52*52

// ---------------- scratch (static device allocations) ----------------
__device__ float               g_wre[OC * KTOT];           // weights, k' = r*512+ch
__device__ float               g_inpad[OC * PADCH + 256];  // padded batch-7 input
__device__ float               g_feat[OC * NPIX];
__device__ float4              g_boxes[NANCH];
__device__ unsigned            g_score[NANCH];
__device__ float               g_hpart[8][54 * NPIX];
__device__ unsigned            g_hist[65536];
__device__ unsigned            g_bsum[256];
__device__ unsigned            g_pref[65536];
__device__ unsigned            g_bfill[65536];
__device__ unsigned long long  g_bkey[NANCH];
__device__ float4              g_sbox[ROWS];
__device__ float               g_area[ROWS];
__device__ unsigned long long  g_maskT[(size_t)NW * ROWS];
__device__ unsigned long long  g_keep[NW];

// packed fp32x2 ops (sm_103a — only reachable via PTX)
#define FMA2(c, a, b) asm("fma.rn.f32x2 %0, %1, %2, %3;" : "=l"(c) : "l"(a), "l"(b), "l"(c))
#define ADD2(c, a, b) asm("add.rn.f32x2 %0, %1, %2;" : "=l"(c) : "l"(a), "l"(b))
__device__ __forceinline__ unsigned long long dup2(float x) {
    unsigned long long d;
    asm("mov.b64 %0, {%1, %1};" : "=l"(d) : "f"(x));
    return d;
}
__device__ __forceinline__ uint32_t smem_u32(const void* p) {
    uint32_t a;
    asm("{ .reg .u64 t; cvta.to.shared.u64 t, %1; cvt.u32.u64 %0, t; }" : "=r"(a) : "l"(p));
    return a;
}
#define CPA16(dst, src) asm volatile("cp.async.cg.shared.global [%0], [%1], 16;" :: "r"(dst), "l"(src))
#define CPA4(dst, src)  asm volatile("cp.async.ca.shared.global [%0], [%1], 4;"  :: "r"(dst), "l"(src))
#define CPCOMMIT()      asm volatile("cp.async.commit_group;" ::: "memory")
#define CPWAIT1()       asm volatile("cp.async.wait_group 1;" ::: "memory")

// ---------------- launch 0: weight transpose (coalesced both sides) + zero hist ----------------
__global__ __launch_bounds__(256) void prep_w_kernel(const float* __restrict__ cw) {
    __shared__ float ws[KTOT / 512 * 512];   // 4608 floats
    int b = blockIdx.x;    // = oc
    int t = threadIdx.x;
    for (int i = t; i < KTOT; i += 256) ws[i] = cw[b * KTOT + i];
    int idx = b * 256 + t;
    if (idx < 65536) g_hist[idx] = 0u;
    else g_bfill[idx - 65536] = 0u;
    __syncthreads();
    for (int k = t; k < KTOT; k += 256) {
        int ch = k & 511, r = k >> 9;
        g_wre[b * KTOT + k] = ws[ch * 9 + r];
    }
}

// ---------------- launch 1: input pad ----------------
__global__ void prep_in_kernel(const float* __restrict__ in7) {
    int j = blockIdx.x * 256 + threadIdx.x;
    if (j >= OC * PADCH) return;
    int c = j / PADCH, rem = j - c * PADCH;
    int y = rem / PADW, x = rem - y * PADW;
    float v = 0.f;
    if (y >= 1 && y <= 50 && x >= 1 && x <= 50)
        v = in7[c * NPIX + (y - 1) * FSZ + (x - 1)];
    g_inpad[j] = v;
}

// ---------------- launch 2: misc setup ----------------
__global__ void setup_misc_kernel() {
    int i = blockIdx.x * 256 + threadIdx.x;
    if (i < ROWS - PRE) {
        g_sbox[PRE + i] = make_float4(0.f, 0.f, 0.f, 0.f);
        g_area[PRE + i] = 1.f;
    }
    if (i < NW) g_keep[i] = 0ull;
}

// ---------------- launch 3: conv 3x3 (batch 7) + leaky relu ----------------
// implicit GEMM 512x2500x4608. CTA = 256 threads = 2 split-K warpgroups x 128.
// CTA tile 128oc x 80px; grid (32,4) = 128 CTAs. Thread tile 8oc x 5 px-pairs.
// B pairs {2pg,2pg+1,16+2pg,17+2pg,32+pg}: 2x LDS.128 + 1x LDS.64 per kk.
// A og-groups (8 rows x 80B) padded to 656B, conflict-free broadcasts.
#define CBK    16
#define NCHK2  144                    // chunks per warpgroup (4608/2/16)
#define A_SZ   10496                  // 16 og-groups * 656B
#define B_OFF  10496
#define STG    15872                  // A 10496 + B 5376
#define WGB    31744                  // 2 stages
#define DSMSZ  63488
extern __shared__ char dsm[];

__global__ __launch_bounds__(256) void conv3_kernel(const float* __restrict__ bias) {
    uint32_t sb = smem_u32(dsm);
    int t = threadIdx.x;
    int wg = t >> 7;                  // 0 / 1
    int wt = t & 127;
    int px0 = blockIdx.x * 80, oc0 = blockIdx.y * 128;
    int og = wt >> 3;                 // 0..15 (8 oc each)
    int pg = wt & 7;                  // 0..7
    int wgk0 = wg * 2304;             // k-range start
    uint32_t wgbase = sb + wg * WGB;

    // pair indices handled by this thread
    int prs[5] = {2 * pg, 2 * pg + 1, 16 + 2 * pg, 17 + 2 * pg, 32 + pg};

    // A staging: 4 x 16B granules per thread (128oc x 4ks = 512 granules)
    int a_oc[4], a_ks[4];
    const float* a_src[4];
    uint32_t a_so[4];
#pragma unroll
    for (int s = 0; s < 4; s++) {
        int idx = wt + 128 * s;
        a_oc[s] = idx >> 2; a_ks[s] = idx & 3;
        a_src[s] = g_wre + (size_t)(oc0 + a_oc[s]) * KTOT + a_ks[s] * 4 + wgk0;
        a_so[s] = (a_oc[s] >> 3) * 656 + (a_oc[s] & 7) * 80 + a_ks[s] * 16;
    }

    // B staging: 10 x 4B per thread (1280 granules = 16kk x 80px, linear c*4)
    int b_kk[10], b_pix[10];
    uint32_t b_so[10];
#pragma unroll
    for (int s = 0; s < 10; s++) {
        int g = wt + 128 * s;
        int kk = g / 80, c = g - 80 * kk;
        int p = px0 + c;
        int py = p / 50, px = p - 50 * py;
        b_kk[s] = kk;
        b_pix[s] = py * PADW + px;
        b_so[s] = B_OFF + kk * 336 + c * 4;
    }

    unsigned long long acc[8][5];
#pragma unroll
    for (int i = 0; i < 8; i++)
#pragma unroll
        for (int j = 0; j < 5; j++) acc[i][j] = 0ull;

    auto issue = [&](int q, int st) {
        int kb = wgk0 + q * CBK;
        int r = kb >> 9, ch0 = kb & 511;
        int ry = r / 3;
        const float* ib = g_inpad + (size_t)ch0 * PADCH + ry * PADW + (r - 3 * ry);
        uint32_t sbase = wgbase + st * STG;
#pragma unroll
        for (int s = 0; s < 4; s++)
            CPA16(sbase + a_so[s], a_src[s] + q * CBK);
#pragma unroll
        for (int s = 0; s < 10; s++)
            CPA4(sbase + b_so[s], ib + (size_t)b_kk[s] * PADCH + b_pix[s]);
    };

    issue(0, 0); CPCOMMIT();
    issue(1, 1); CPCOMMIT();

    int barid = wg + 1;
    for (int q = 0; q < NCHK2; q++) {
        int st = q & 1;
        CPWAIT1();
        asm volatile("bar.sync %0, 128;" :: "r"(barid) : "memory");
        const char* A_ = dsm + wg * WGB + st * STG + og * 656;
        const char* B_ = dsm + wg * WGB + st * STG + B_OFF;

        // b2 double buffer: preload kk=0 (2x LDS.128 + 1x LDS.64)
        unsigned long long b2c[5], b2n[5];
        {
            ulonglong2 u0 = *(const ulonglong2*)(B_ + pg * 16);
            ulonglong2 u1 = *(const ulonglong2*)(B_ + 128 + pg * 16);
            b2c[0] = u0.x; b2c[1] = u0.y;
            b2c[2] = u1.x; b2c[3] = u1.y;
            b2c[4] = *(const unsigned long long*)(B_ + 256 + pg * 8);
        }

#pragma unroll
        for (int kk4 = 0; kk4 < CBK; kk4 += 4) {
            float4 av[8];
#pragma unroll
            for (int i = 0; i < 8; i++)
                av[i] = *(const float4*)(A_ + i * 80 + kk4 * 4);
#pragma unroll
            for (int kk = 0; kk < 4; kk++) {
                int gk = kk4 + kk;
                if (gk < CBK - 1) {
                    const char* brow = B_ + (gk + 1) * 336;
                    ulonglong2 u0 = *(const ulonglong2*)(brow + pg * 16);
                    ulonglong2 u1 = *(const ulonglong2*)(brow + 128 + pg * 16);
                    b2n[0] = u0.x; b2n[1] = u0.y;
                    b2n[2] = u1.x; b2n[3] = u1.y;
                    b2n[4] = *(const unsigned long long*)(brow + 256 + pg * 8);
                }
#pragma unroll
                for (int i = 0; i < 8; i++) {
                    float afv = (kk == 0) ? av[i].x : (kk == 1) ? av[i].y
                              : (kk == 2) ? av[i].z : av[i].w;
                    unsigned long long da = dup2(afv);
#pragma unroll
                    for (int j = 0; j < 5; j++)
                        FMA2(acc[i][j], da, b2c[j]);
                }
                if (gk < CBK - 1) {
#pragma unroll
                    for (int j = 0; j < 5; j++) b2c[j] = b2n[j];
                }
            }
        }
        // issue next-next chunk into the stage just freed
        asm volatile("bar.sync %0, 128;" :: "r"(barid) : "memory");
        if (q + 2 < NCHK2) issue(q + 2, st);
        CPCOMMIT();
    }

    // combine split-K halves (reuse stage smem), wg0 finishes
    __syncthreads();
    unsigned long long* epi = (unsigned long long*)dsm;
    if (wg == 1) {
#pragma unroll
        for (int i = 0; i < 8; i++)
#pragma unroll
            for (int j = 0; j < 5; j++) epi[wt * 41 + i * 5 + j] = acc[i][j];
    }
    __syncthreads();
    if (wg == 0) {
#pragma unroll
        for (int i = 0; i < 8; i++) {
            int oc = oc0 + og * 8 + i;
            float bv = bias[oc];
#pragma unroll
            for (int j = 0; j < 5; j++) {
                ADD2(acc[i][j], acc[i][j], epi[wt * 41 + i * 5 + j]);
                int p = px0 + 2 * prs[j];
                if (p < NPIX) {   // NPIX even -> pair-granular validity
                    float lo, hi;
                    asm("mov.b64 {%0, %1}, %2;" : "=f"(lo), "=f"(hi) : "l"(acc[i][j]));
                    lo += bv; hi += bv;
                    lo = (lo >= 0.f) ? lo : 0.01f * lo;
                    hi = (hi >= 0.f) ? hi : 0.01f * hi;
                    *(float2*)&g_feat[(size_t)oc * NPIX + p] = make_float2(lo, hi);
                }
            }
        }
    }
}

// ---------------- heads part 1: 1x1 convs, 8 channel-groups of 64 ----------------
// grid (20, 8): 160 blocks, 128 px/block, all threads active.
__global__ __launch_bounds__(128) void heads_part_kernel(const float* __restrict__ reg_w,
                                                         const float* __restrict__ cls_w) {
    __shared__ float wsm[64][56];
    int t = threadIdx.x;
    int cg = blockIdx.y;
    int c0 = cg * 64;
    int p = blockIdx.x * 128 + t;

    for (int i = t; i < 54 * 64; i += 128) {
        int o = i >> 6, c = i & 63;
        float v = (o < 36) ? reg_w[o * 512 + c0 + c] : cls_w[(o - 36) * 512 + c0 + c];
        wsm[c][o] = v;
    }
    __syncthreads();

    float acc[54];
#pragma unroll
    for (int o = 0; o < 54; o++) acc[o] = 0.f;
    if (p < NPIX) {
        for (int c = 0; c < 64; c++) {
            float f = g_feat[(size_t)(c0 + c) * NPIX + p];
#pragma unroll
            for (int o = 0; o < 54; o++) acc[o] += f * wsm[c][o];
        }
#pragma unroll
        for (int o = 0; o < 54; o++)
            g_hpart[cg][o * NPIX + p] = acc[o];
    }
}

// ---------------- heads part 2: combine + softmax + decode + scores + histogram ----------------
__global__ __launch_bounds__(128) void heads_fin_kernel(const float* __restrict__ reg_b,
                                                        const float* __restrict__ cls_b) {
    int p = blockIdx.x * 128 + threadIdx.x;
    if (p >= NPIX) return;
    float acc[54];
#pragma unroll
    for (int o = 0; o < 54; o++) {
        float s01 = g_hpart[0][o * NPIX + p] + g_hpart[1][o * NPIX + p];
        float s23 = g_hpart[2][o * NPIX + p] + g_hpart[3][o * NPIX + p];
        float s45 = g_hpart[4][o * NPIX + p] + g_hpart[5][o * NPIX + p];
        float s67 = g_hpart[6][o * NPIX + p] + g_hpart[7][o * NPIX + p];
        acc[o] = (s01 + s23) + (s45 + s67);
    }
#pragma unroll
    for (int o = 0; o < 36; o++) acc[o] += reg_b[o];
#pragma unroll
    for (int o = 0; o < 18; o++) acc[36 + o] += cls_b[o];

    int pq = p / FSZ, pr = p - pq * FSZ;
    float cxv = 16.f * (float)pq + 8.f;
    float cyv = 16.f * (float)pr + 8.f;
    const float ssv[3]  = {8.f, 16.f, 32.f};
    const float sqr[3]  = {0.70710678f, 1.0f, 1.41421356f};
    const float sqi[3]  = {1.41421356f, 1.0f, 0.70710678f};
    const float NEGINF = __int_as_float(0xff800000);

#pragma unroll
    for (int k = 0; k < 9; k++) {
        float pr0 = acc[k * 4 + 0], pr1 = acc[k * 4 + 1];
        float pr2 = acc[k * 4 + 2], pr3 = acc[k * 4 + 3];
        float l0 = acc[36 + k * 2], l1 = acc[36 + k * 2 + 1];
        float m  = fmaxf(l0, l1);
        float e0 = expf(l0 - m), e1 = expf(l1 - m);
        float sc = e1 / (e0 + e1);

        int ri = k / 3, si = k - 3 * ri;
        float hk = (16.f * ssv[si]) * sqr[ri];
        float wk = (16.f * ssv[si]) * sqi[ri];
        float ax1 = cxv - wk * 0.5f;
        float ay1 = cyv - hk * 0.5f;
        const float hi = 799.f;
        float rx1 = fminf(fmaxf(pr0 + ax1, 0.f), hi);
        float ry1 = fminf(fmaxf(pr1 + ay1, 0.f), hi);
        float rx2 = fminf(fmaxf(((pr0 + ax1) + pr2) + wk, 0.f), hi);
        float ry2 = fminf(fmaxf(((pr1 + ay1) + pr3) + hk, 0.f), hi);
        float wv = pr2 + wk, hv = pr3 + hk;
        bool valid = (wv >= 16.f) && (hv >= 16.f);
        float s = valid ? sc : NEGINF;

        int a = p * 9 + k;
        g_boxes[a] = make_float4(rx1, ry1, rx2, ry2);
        unsigned u = __float_as_uint(s);
        u = (u >> 31) ? ~u : (u | 0x80000000u);
        g_score[a] = u;
        atomicAdd(&g_hist[u >> 16], 1u);
    }
}

// ---------------- bucket sums (coalesced) ----------------
__global__ __launch_bounds__(256) void bucket_sum_kernel() {
    __shared__ unsigned sh[256];
    int b = blockIdx.x, t = threadIdx.x;
    sh[t] = g_hist[b * 256 + t];
    __syncthreads();
    for (int off = 128; off; off >>= 1) {
        if (t < off) sh[t] += sh[t + off];
        __syncthreads();
    }
    if (t == 0) g_bsum[b] = sh[0];
}

// ---------------- suffix-prefix per bucket (coalesced) ----------------
__global__ __launch_bounds__(256) void bucket_pref_kernel() {
    __shared__ unsigned sh[256];
    __shared__ unsigned above_s;
    int b = blockIdx.x, t = threadIdx.x;
    unsigned v = (t > b) ? g_bsum[t] : 0u;
    sh[t] = v;
    __syncthreads();
    for (int off = 128; off; off >>= 1) {
        if (t < off) sh[t] += sh[t + off];
        __syncthreads();
    }
    if (t == 0) above_s = sh[0];
    __syncthreads();
    unsigned above = above_s;
    unsigned h = g_hist[b * 256 + t];
    __syncthreads();
    sh[t] = h;
    __syncthreads();
    for (int off = 1; off < 256; off <<= 1) {
        unsigned x = (t + off < 256) ? sh[t + off] : 0u;
        __syncthreads();
        sh[t] += x;
        __syncthreads();
    }
    g_pref[b * 256 + t] = above + sh[t] - h;   // count strictly higher
}

// ---------------- bucket fill (only buckets that can reach top-6000) ----------------
__global__ void bucket_fill_kernel() {
    int i = blockIdx.x * 256 + threadIdx.x;
    if (i >= NANCH) return;
    unsigned s = g_score[i];
    unsigned b = s >> 16;
    unsigned base = g_pref[b];
    if (base >= PRE) return;
    unsigned slot = atomicAdd(&g_bfill[b], 1u);
    g_bkey[base + slot] = ((unsigned long long)s << 32) | (unsigned)(~i);
}

// ---------------- exact rank + scatter ----------------
__global__ void rank_scatter_kernel() {
    int i = blockIdx.x * 256 + threadIdx.x;
    if (i >= NANCH) return;
    unsigned s = g_score[i];
    unsigned b = s >> 16;
    unsigned base = g_pref[b];
    if (base >= PRE) return;
    unsigned cnt = g_hist[b];
    unsigned long long my = ((unsigned long long)s << 32) | (unsigned)(~i);
    unsigned r = base;
    for (unsigned q = 0; q < cnt; q++)
        r += (g_bkey[base + q] > my);
    if (r < PRE) {
        float4 bx = g_boxes[i];
        g_sbox[r] = bx;
        g_area[r] = (bx.z - bx.x + 1.f) * (bx.w - bx.y + 1.f);
    }
}

// ---------------- NMS mask, transposed layout (yy2 = max bug preserved) ----------------
// division-free: ov > 0.7  <=>  (den>0 && inter > 0.7*den) || (den==0 && inter>0)
// 256 threads cover 4 j-tiles per block; grid (24, 94), early-out below diagonal.
__global__ __launch_bounds__(256) void nms_mask_kernel() {
    int gi = blockIdx.y;
    int jb = blockIdx.x * 4;
    if (jb + 3 < gi) return;
    __shared__ float4 cbx[4][64];
    __shared__ float  car[4][64];
    int t = threadIdx.x;
    int jt = t >> 6, tt = t & 63;
    int gj = jb + jt;
    if (gj < NW) {
        cbx[jt][tt] = g_sbox[gj * 64 + tt];
        car[jt][tt] = g_area[gj * 64 + tt];
    }
    __syncthreads();
    if (gj < gi || gj >= NW) return;
    int i = gi * 64 + tt;
    float4 bi = g_sbox[i];
    float  ai = g_area[i];
    unsigned long long word = 0;
#pragma unroll 8
    for (int jj = 0; jj < 64; jj++) {
        float4 bj = cbx[jt][jj];
        float xx1 = fmaxf(bi.x, bj.x);
        float yy1 = fmaxf(bi.y, bj.y);
        float xx2 = fminf(bi.z, bj.z);
        float yy2 = fmaxf(bi.w, bj.w);   // reference bug: maximum, not minimum
        float w = fmaxf(0.f, xx2 - xx1 + 1.f);
        float h = fmaxf(0.f, yy2 - yy1 + 1.f);
        float inter = w * h;
        float den = ai + car[jt][jj] - inter;
        bool sup = (den > 0.f) ? (inter > 0.7f * den) : ((den == 0.f) && (inter > 0.f));
        word |= ((unsigned long long)sup) << jj;
    }
    g_maskT[(size_t)gj * ROWS + i] = word;   // coalesced across tt
}

// ---------------- greedy NMS scan (ffs skip-loop, 8-wide MLP) ----------------
__global__ __launch_bounds__(128) void nms_scan_kernel() {
    __shared__ unsigned long long ms[64];
    __shared__ unsigned long long s_remv, s_kept;
    int t = threadIdx.x;
    unsigned long long remv = 0;                       // thread t owns word g=t
    unsigned long long nextdiag = (t < 64) ? g_maskT[t] : 0ull;
    for (int cb = 0; cb < NW; cb++) {
        if (t < 64) ms[t] = nextdiag;
        if (t == cb) s_remv = remv;
        __syncthreads();
        if (t < 64 && cb + 1 < NW)
            nextdiag = g_maskT[(size_t)(cb + 1) * ROWS + (cb + 1) * 64 + t];
        if (t == 0) {
            unsigned long long v = s_remv, kept = 0ull;
            int lim = PRE - cb * 64; if (lim > 64) lim = 64;
            unsigned long long avail = ~v;
            if (lim < 64) avail &= (1ull << lim) - 1ull;
            while (avail) {
                int j = __ffsll((long long)avail) - 1;
                kept |= 1ull << j;
                v |= ms[j];
                avail &= ~v;
                avail &= (j < 63) ? (~0ull << (j + 1)) : 0ull;
            }
            s_kept = kept;
            g_keep[cb] = kept;
        }
        __syncthreads();
        if (t > cb && t < NW) {
            unsigned long long kk = s_kept;
            const unsigned long long* rowT = g_maskT + (size_t)t * ROWS + cb * 64;
            while (kk) {
                unsigned long long m[8];
#pragma unroll
                for (int u = 0; u < 8; u++) m[u] = 0ull;
#pragma unroll
                for (int u = 0; u < 8; u++) {
                    if (!kk) break;
                    int j = __ffsll((long long)kk) - 1; kk &= kk - 1;
                    m[u] = rowT[j];
                }
                remv |= ((m[0] | m[1]) | (m[2] | m[3])) |
                        ((m[4] | m[5]) | (m[6] | m[7]));
            }
        }
    }
}

// ---------------- emit top-300 ----------------
__global__ __launch_bounds__(256) void output_kernel(float* __restrict__ out) {
    __shared__ int cnts[256];
    __shared__ int offs[256];
    __shared__ int Ktot;
    int t = threadIdx.x;
    int lo = t * 24;
    int hi = lo + 24; if (hi > PRE) hi = PRE;
    int c = 0;
    for (int i = lo; i < hi; i++)
        c += (int)((g_keep[i >> 6] >> (i & 63)) & 1ull);
    cnts[t] = c;
    __syncthreads();
    if (t == 0) {
        int r = 0;
        for (int q = 0; q < 256; q++) { offs[q] = r; r += cnts[q]; }
        Ktot = r;
    }
    __syncthreads();
    int K = Ktot;
    int pk = offs[t];
    for (int i = lo; i < hi; i++) {
        bool kept = (g_keep[i >> 6] >> (i & 63)) & 1ull;
        int pos = kept ? pk : (K + (i - pk));
        if (kept) pk++;
        if (pos < POST) {
            float4 b = g_sbox[i];
            out[pos * 4 + 0] = b.x;
            out[pos * 4 + 1] = b.y;
            out[pos * 4 + 2] = b.z - b.x + 1.f;
            out[pos * 4 + 3] = b.w - b.y + 1.f;
        }
    }
}

// ---------------- launch ----------------
extern "C" void kernel_launch(void* const* d_in, const int* in_sizes, int n_in,
                              void* d_out, int out_size) {
    const float* in_features = (const float*)d_in[0];
    const float* conv_w = (const float*)d_in[1];
    const float* conv_b = (const float*)d_in[2];
    const float* reg_w  = (const float*)d_in[3];
    const float* reg_b  = (const float*)d_in[4];
    const float* cls_w  = (const float*)d_in[5];
    const float* cls_b  = (const float*)d_in[6];
    float* out = (float*)d_out;

    // only batch index 7 feeds the output
    const float* in7 = in_features + (size_t)7 * 512 * NPIX;

    cudaFuncSetAttribute(conv3_kernel,
                         cudaFuncAttributeMaxDynamicSharedMemorySize, DSMSZ);

    prep_w_kernel<<<512, 256>>>(conv_w);                         // 0
    prep_in_kernel<<<(OC * PADCH + 255) / 256, 256>>>(in7);      // 1
    setup_misc_kernel<<<1, 256>>>();                             // 2
    conv3_kernel<<<dim3(32, 4), 256, DSMSZ>>>(conv_b);           // 3 <- profiled
    heads_part_kernel<<<dim3(20, 8), 128>>>(reg_w, cls_w);       // 4
    heads_fin_kernel<<<20, 128>>>(reg_b, cls_b);                 // 5
    bucket_sum_kernel<<<256, 256>>>();                           // 6
    bucket_pref_kernel<<<256, 256>>>();                          // 7
    bucket_fill_kernel<<<88, 256>>>();                           // 8
    rank_scatter_kernel<<<88, 256>>>();                          // 9
    nms_mask_kernel<<<dim3(24, NW), 256>>>();                    // 10
    nms_scan_kernel<<<1, 128>>>();                               // 11
    output_kernel<<<1, 256>>>(out);                              // 12
}

// round 17
// speedup vs baseline: 1.0966x; 1.0190x over previous
#include <cuda_runtime.h>
#include <cstdint>

#define FSZ   50
#define NPIX  2500
#define OC    512
#define KTOT  4608      // 512*9
#define NANCH 22500     // 2500*9
#define PRE   6000
#define NW    94        // ceil(6000/64)
#define ROWS  6016
#define POST  300
#define PADW  52
#define PADCH 2704      // 52*52

// ---------------- scratch (static device allocations) ----------------
__device__ float               g_wre[OC * KTOT];           // weights, k' = r*512+ch
__device__ float               g_inpad[OC * PADCH + 256];  // padded batch-7 input
__device__ float               g_feat[OC * NPIX];
__device__ float4              g_boxes[NANCH];
__device__ unsigned            g_score[NANCH];
__device__ float               g_hpart[8][54 * NPIX];
__device__ unsigned            g_hist[65536];
__device__ unsigned            g_bsum[256];
__device__ unsigned            g_pref[65536];
__device__ unsigned            g_bfill[65536];
__device__ unsigned long long  g_bkey[NANCH];
__device__ float4              g_sbox[ROWS];
__device__ float               g_area[ROWS];
__device__ unsigned long long  g_maskT[(size_t)NW * ROWS];

// packed fp32x2 ops (sm_103a — only reachable via PTX)
#define FMA2(c, a, b) asm("fma.rn.f32x2 %0, %1, %2, %3;" : "=l"(c) : "l"(a), "l"(b), "l"(c))
#define ADD2(c, a, b) asm("add.rn.f32x2 %0, %1, %2;" : "=l"(c) : "l"(a), "l"(b))
__device__ __forceinline__ unsigned long long dup2(float x) {
    unsigned long long d;
    asm("mov.b64 %0, {%1, %1};" : "=l"(d) : "f"(x));
    return d;
}
__device__ __forceinline__ uint32_t smem_u32(const void* p) {
    uint32_t a;
    asm("{ .reg .u64 t; cvta.to.shared.u64 t, %1; cvt.u32.u64 %0, t; }" : "=r"(a) : "l"(p));
    return a;
}
#define CPA16(dst, src) asm volatile("cp.async.cg.shared.global [%0], [%1], 16;" :: "r"(dst), "l"(src))
#define CPA4(dst, src)  asm volatile("cp.async.ca.shared.global [%0], [%1], 4;"  :: "r"(dst), "l"(src))
#define CPCOMMIT()      asm volatile("cp.async.commit_group;" ::: "memory")
#define CPWAIT1()       asm volatile("cp.async.wait_group 1;" ::: "memory")

// ---------------- launch 0: weight transpose (coalesced both sides) + zero hist ----------------
__global__ __launch_bounds__(256) void prep_w_kernel(const float* __restrict__ cw) {
    __shared__ float ws[KTOT / 512 * 512];   // 4608 floats
    int b = blockIdx.x;    // = oc
    int t = threadIdx.x;
    for (int i = t; i < KTOT; i += 256) ws[i] = cw[b * KTOT + i];
    int idx = b * 256 + t;
    if (idx < 65536) g_hist[idx] = 0u;
    else g_bfill[idx - 65536] = 0u;
    __syncthreads();
    for (int k = t; k < KTOT; k += 256) {
        int ch = k & 511, r = k >> 9;
        g_wre[b * KTOT + k] = ws[ch * 9 + r];
    }
}

// ---------------- launch 1: input pad ----------------
__global__ void prep_in_kernel(const float* __restrict__ in7) {
    int j = blockIdx.x * 256 + threadIdx.x;
    if (j >= OC * PADCH) return;
    int c = j / PADCH, rem = j - c * PADCH;
    int y = rem / PADW, x = rem - y * PADW;
    float v = 0.f;
    if (y >= 1 && y <= 50 && x >= 1 && x <= 50)
        v = in7[c * NPIX + (y - 1) * FSZ + (x - 1)];
    g_inpad[j] = v;
}

// ---------------- launch 2: sbox pad ----------------
__global__ void setup_pad_kernel() {
    int i = threadIdx.x;
    if (i < ROWS - PRE) {
        g_sbox[PRE + i] = make_float4(0.f, 0.f, 0.f, 0.f);
        g_area[PRE + i] = 1.f;
    }
}

// ---------------- launch 3: conv 3x3 (batch 7) + leaky relu ----------------
// implicit GEMM 512x2500x4608. CTA = 256 threads = 2 split-K warpgroups x 128.
// CTA tile 128oc x 80px; grid (32,4) = 128 CTAs. Thread tile 8oc x 5 px-pairs.
// B pairs {2pg,2pg+1,16+2pg,17+2pg,32+pg}: 2x LDS.128 + 1x LDS.64 per kk.
// A og-groups (8 rows x 80B) padded to 656B, conflict-free broadcasts.
#define CBK    16
#define NCHK2  144                    // chunks per warpgroup (4608/2/16)
#define A_SZ   10496                  // 16 og-groups * 656B
#define B_OFF  10496
#define STG    15872                  // A 10496 + B 5376
#define WGB    31744                  // 2 stages
#define DSMSZ  63488
extern __shared__ char dsm[];

__global__ __launch_bounds__(256) void conv3_kernel(const float* __restrict__ bias) {
    uint32_t sb = smem_u32(dsm);
    int t = threadIdx.x;
    int wg = t >> 7;                  // 0 / 1
    int wt = t & 127;
    int px0 = blockIdx.x * 80, oc0 = blockIdx.y * 128;
    int og = wt >> 3;                 // 0..15 (8 oc each)
    int pg = wt & 7;                  // 0..7
    int wgk0 = wg * 2304;             // k-range start
    uint32_t wgbase = sb + wg * WGB;

    // pair indices handled by this thread
    int prs[5] = {2 * pg, 2 * pg + 1, 16 + 2 * pg, 17 + 2 * pg, 32 + pg};

    // A staging: 4 x 16B granules per thread (128oc x 4ks = 512 granules)
    int a_oc[4], a_ks[4];
    const float* a_src[4];
    uint32_t a_so[4];
#pragma unroll
    for (int s = 0; s < 4; s++) {
        int idx = wt + 128 * s;
        a_oc[s] = idx >> 2; a_ks[s] = idx & 3;
        a_src[s] = g_wre + (size_t)(oc0 + a_oc[s]) * KTOT + a_ks[s] * 4 + wgk0;
        a_so[s] = (a_oc[s] >> 3) * 656 + (a_oc[s] & 7) * 80 + a_ks[s] * 16;
    }

    // B staging: 10 x 4B per thread (1280 granules = 16kk x 80px, linear c*4)
    int b_kk[10], b_pix[10];
    uint32_t b_so[10];
#pragma unroll
    for (int s = 0; s < 10; s++) {
        int g = wt + 128 * s;
        int kk = g / 80, c = g - 80 * kk;
        int p = px0 + c;
        int py = p / 50, px = p - 50 * py;
        b_kk[s] = kk;
        b_pix[s] = py * PADW + px;
        b_so[s] = B_OFF + kk * 336 + c * 4;
    }

    unsigned long long acc[8][5];
#pragma unroll
    for (int i = 0; i < 8; i++)
#pragma unroll
        for (int j = 0; j < 5; j++) acc[i][j] = 0ull;

    auto issue = [&](int q, int st) {
        int kb = wgk0 + q * CBK;
        int r = kb >> 9, ch0 = kb & 511;
        int ry = r / 3;
        const float* ib = g_inpad + (size_t)ch0 * PADCH + ry * PADW + (r - 3 * ry);
        uint32_t sbase = wgbase + st * STG;
#pragma unroll
        for (int s = 0; s < 4; s++)
            CPA16(sbase + a_so[s], a_src[s] + q * CBK);
#pragma unroll
        for (int s = 0; s < 10; s++)
            CPA4(sbase + b_so[s], ib + (size_t)b_kk[s] * PADCH + b_pix[s]);
    };

    issue(0, 0); CPCOMMIT();
    issue(1, 1); CPCOMMIT();

    int barid = wg + 1;
    for (int q = 0; q < NCHK2; q++) {
        int st = q & 1;
        CPWAIT1();
        asm volatile("bar.sync %0, 128;" :: "r"(barid) : "memory");
        const char* A_ = dsm + wg * WGB + st * STG + og * 656;
        const char* B_ = dsm + wg * WGB + st * STG + B_OFF;

        // b2 double buffer: preload kk=0 (2x LDS.128 + 1x LDS.64)
        unsigned long long b2c[5], b2n[5];
        {
            ulonglong2 u0 = *(const ulonglong2*)(B_ + pg * 16);
            ulonglong2 u1 = *(const ulonglong2*)(B_ + 128 + pg * 16);
            b2c[0] = u0.x; b2c[1] = u0.y;
            b2c[2] = u1.x; b2c[3] = u1.y;
            b2c[4] = *(const unsigned long long*)(B_ + 256 + pg * 8);
        }

#pragma unroll
        for (int kk4 = 0; kk4 < CBK; kk4 += 4) {
            float4 av[8];
#pragma unroll
            for (int i = 0; i < 8; i++)
                av[i] = *(const float4*)(A_ + i * 80 + kk4 * 4);
#pragma unroll
            for (int kk = 0; kk < 4; kk++) {
                int gk = kk4 + kk;
                if (gk < CBK - 1) {
                    const char* brow = B_ + (gk + 1) * 336;
                    ulonglong2 u0 = *(const ulonglong2*)(brow + pg * 16);
                    ulonglong2 u1 = *(const ulonglong2*)(brow + 128 + pg * 16);
                    b2n[0] = u0.x; b2n[1] = u0.y;
                    b2n[2] = u1.x; b2n[3] = u1.y;
                    b2n[4] = *(const unsigned long long*)(brow + 256 + pg * 8);
                }
#pragma unroll
                for (int i = 0; i < 8; i++) {
                    float afv = (kk == 0) ? av[i].x : (kk == 1) ? av[i].y
                              : (kk == 2) ? av[i].z : av[i].w;
                    unsigned long long da = dup2(afv);
#pragma unroll
                    for (int j = 0; j < 5; j++)
                        FMA2(acc[i][j], da, b2c[j]);
                }
                if (gk < CBK - 1) {
#pragma unroll
                    for (int j = 0; j < 5; j++) b2c[j] = b2n[j];
                }
            }
        }
        // issue next-next chunk into the stage just freed
        asm volatile("bar.sync %0, 128;" :: "r"(barid) : "memory");
        if (q + 2 < NCHK2) issue(q + 2, st);
        CPCOMMIT();
    }

    // combine split-K halves (reuse stage smem), wg0 finishes
    __syncthreads();
    unsigned long long* epi = (unsigned long long*)dsm;
    if (wg == 1) {
#pragma unroll
        for (int i = 0; i < 8; i++)
#pragma unroll
            for (int j = 0; j < 5; j++) epi[wt * 41 + i * 5 + j] = acc[i][j];
    }
    __syncthreads();
    if (wg == 0) {
#pragma unroll
        for (int i = 0; i < 8; i++) {
            int oc = oc0 + og * 8 + i;
            float bv = bias[oc];
#pragma unroll
            for (int j = 0; j < 5; j++) {
                ADD2(acc[i][j], acc[i][j], epi[wt * 41 + i * 5 + j]);
                int p = px0 + 2 * prs[j];
                if (p < NPIX) {   // NPIX even -> pair-granular validity
                    float lo, hi;
                    asm("mov.b64 {%0, %1}, %2;" : "=f"(lo), "=f"(hi) : "l"(acc[i][j]));
                    lo += bv; hi += bv;
                    lo = (lo >= 0.f) ? lo : 0.01f * lo;
                    hi = (hi >= 0.f) ? hi : 0.01f * hi;
                    *(float2*)&g_feat[(size_t)oc * NPIX + p] = make_float2(lo, hi);
                }
            }
        }
    }
}

// ---------------- heads part 1: 1x1 convs, 8 channel-groups of 64 ----------------
// grid (20, 8): 160 blocks, 128 px/block, all threads active.
__global__ __launch_bounds__(128) void heads_part_kernel(const float* __restrict__ reg_w,
                                                         const float* __restrict__ cls_w) {
    __shared__ float wsm[64][56];
    int t = threadIdx.x;
    int cg = blockIdx.y;
    int c0 = cg * 64;
    int p = blockIdx.x * 128 + t;

    for (int i = t; i < 54 * 64; i += 128) {
        int o = i >> 6, c = i & 63;
        float v = (o < 36) ? reg_w[o * 512 + c0 + c] : cls_w[(o - 36) * 512 + c0 + c];
        wsm[c][o] = v;
    }
    __syncthreads();

    float acc[54];
#pragma unroll
    for (int o = 0; o < 54; o++) acc[o] = 0.f;
    if (p < NPIX) {
        for (int c = 0; c < 64; c++) {
            float f = g_feat[(size_t)(c0 + c) * NPIX + p];
#pragma unroll
            for (int o = 0; o < 54; o++) acc[o] += f * wsm[c][o];
        }
#pragma unroll
        for (int o = 0; o < 54; o++)
            g_hpart[cg][o * NPIX + p] = acc[o];
    }
}

// ---------------- heads part 2: combine + softmax + decode + scores + histogram ----------------
// grid 40 x 64 threads (engage more SMs)
__global__ __launch_bounds__(64) void heads_fin_kernel(const float* __restrict__ reg_b,
                                                       const float* __restrict__ cls_b) {
    int p = blockIdx.x * 64 + threadIdx.x;
    if (p >= NPIX) return;
    float acc[54];
#pragma unroll
    for (int o = 0; o < 54; o++) {
        float s01 = g_hpart[0][o * NPIX + p] + g_hpart[1][o * NPIX + p];
        float s23 = g_hpart[2][o * NPIX + p] + g_hpart[3][o * NPIX + p];
        float s45 = g_hpart[4][o * NPIX + p] + g_hpart[5][o * NPIX + p];
        float s67 = g_hpart[6][o * NPIX + p] + g_hpart[7][o * NPIX + p];
        acc[o] = (s01 + s23) + (s45 + s67);
    }
#pragma unroll
    for (int o = 0; o < 36; o++) acc[o] += reg_b[o];
#pragma unroll
    for (int o = 0; o < 18; o++) acc[36 + o] += cls_b[o];

    int pq = p / FSZ, pr = p - pq * FSZ;
    float cxv = 16.f * (float)pq + 8.f;
    float cyv = 16.f * (float)pr + 8.f;
    const float ssv[3]  = {8.f, 16.f, 32.f};
    const float sqr[3]  = {0.70710678f, 1.0f, 1.41421356f};
    const float sqi[3]  = {1.41421356f, 1.0f, 0.70710678f};
    const float NEGINF = __int_as_float(0xff800000);

#pragma unroll
    for (int k = 0; k < 9; k++) {
        float pr0 = acc[k * 4 + 0], pr1 = acc[k * 4 + 1];
        float pr2 = acc[k * 4 + 2], pr3 = acc[k * 4 + 3];
        float l0 = acc[36 + k * 2], l1 = acc[36 + k * 2 + 1];
        float m  = fmaxf(l0, l1);
        float e0 = expf(l0 - m), e1 = expf(l1 - m);
        float sc = e1 / (e0 + e1);

        int ri = k / 3, si = k - 3 * ri;
        float hk = (16.f * ssv[si]) * sqr[ri];
        float wk = (16.f * ssv[si]) * sqi[ri];
        float ax1 = cxv - wk * 0.5f;
        float ay1 = cyv - hk * 0.5f;
        const float hi = 799.f;
        float rx1 = fminf(fmaxf(pr0 + ax1, 0.f), hi);
        float ry1 = fminf(fmaxf(pr1 + ay1, 0.f), hi);
        float rx2 = fminf(fmaxf(((pr0 + ax1) + pr2) + wk, 0.f), hi);
        float ry2 = fminf(fmaxf(((pr1 + ay1) + pr3) + hk, 0.f), hi);
        float wv = pr2 + wk, hv = pr3 + hk;
        bool valid = (wv >= 16.f) && (hv >= 16.f);
        float s = valid ? sc : NEGINF;

        int a = p * 9 + k;
        g_boxes[a] = make_float4(rx1, ry1, rx2, ry2);
        unsigned u = __float_as_uint(s);
        u = (u >> 31) ? ~u : (u | 0x80000000u);
        g_score[a] = u;
        atomicAdd(&g_hist[u >> 16], 1u);
    }
}

// ---------------- bucket sums (coalesced) ----------------
__global__ __launch_bounds__(256) void bucket_sum_kernel() {
    __shared__ unsigned sh[256];
    int b = blockIdx.x, t = threadIdx.x;
    sh[t] = g_hist[b * 256 + t];
    __syncthreads();
    for (int off = 128; off; off >>= 1) {
        if (t < off) sh[t] += sh[t + off];
        __syncthreads();
    }
    if (t == 0) g_bsum[b] = sh[0];
}

// ---------------- suffix-prefix per bucket (coalesced) ----------------
__global__ __launch_bounds__(256) void bucket_pref_kernel() {
    __shared__ unsigned sh[256];
    __shared__ unsigned above_s;
    int b = blockIdx.x, t = threadIdx.x;
    unsigned v = (t > b) ? g_bsum[t] : 0u;
    sh[t] = v;
    __syncthreads();
    for (int off = 128; off; off >>= 1) {
        if (t < off) sh[t] += sh[t + off];
        __syncthreads();
    }
    if (t == 0) above_s = sh[0];
    __syncthreads();
    unsigned above = above_s;
    unsigned h = g_hist[b * 256 + t];
    __syncthreads();
    sh[t] = h;
    __syncthreads();
    for (int off = 1; off < 256; off <<= 1) {
        unsigned x = (t + off < 256) ? sh[t + off] : 0u;
        __syncthreads();
        sh[t] += x;
        __syncthreads();
    }
    g_pref[b * 256 + t] = above + sh[t] - h;   // count strictly higher
}

// ---------------- bucket fill (only buckets that can reach top-6000) ----------------
__global__ void bucket_fill_kernel() {
    int i = blockIdx.x * 256 + threadIdx.x;
    if (i >= NANCH) return;
    unsigned s = g_score[i];
    unsigned b = s >> 16;
    unsigned base = g_pref[b];
    if (base >= PRE) return;
    unsigned slot = atomicAdd(&g_bfill[b], 1u);
    g_bkey[base + slot] = ((unsigned long long)s << 32) | (unsigned)(~i);
}

// ---------------- exact rank + scatter ----------------
__global__ void rank_scatter_kernel() {
    int i = blockIdx.x * 256 + threadIdx.x;
    if (i >= NANCH) return;
    unsigned s = g_score[i];
    unsigned b = s >> 16;
    unsigned base = g_pref[b];
    if (base >= PRE) return;
    unsigned cnt = g_hist[b];
    unsigned long long my = ((unsigned long long)s << 32) | (unsigned)(~i);
    unsigned r = base;
    for (unsigned q = 0; q < cnt; q++)
        r += (g_bkey[base + q] > my);
    if (r < PRE) {
        float4 bx = g_boxes[i];
        g_sbox[r] = bx;
        g_area[r] = (bx.z - bx.x + 1.f) * (bx.w - bx.y + 1.f);
    }
}

// ---------------- NMS mask, transposed layout (yy2 = max bug preserved) ----------------
// division-free: ov > 0.7  <=>  (den>0 && inter > 0.7*den) || (den==0 && inter>0)
// 256 threads cover 4 j-tiles per block; grid (24, 94), early-out below diagonal.
__global__ __launch_bounds__(256) void nms_mask_kernel() {
    int gi = blockIdx.y;
    int jb = blockIdx.x * 4;
    if (jb + 3 < gi) return;
    __shared__ float4 cbx[4][64];
    __shared__ float  car[4][64];
    int t = threadIdx.x;
    int jt = t >> 6, tt = t & 63;
    int gj = jb + jt;
    if (gj < NW) {
        cbx[jt][tt] = g_sbox[gj * 64 + tt];
        car[jt][tt] = g_area[gj * 64 + tt];
    }
    __syncthreads();
    if (gj < gi || gj >= NW) return;
    int i = gi * 64 + tt;
    float4 bi = g_sbox[i];
    float  ai = g_area[i];
    unsigned long long word = 0;
#pragma unroll 8
    for (int jj = 0; jj < 64; jj++) {
        float4 bj = cbx[jt][jj];
        float xx1 = fmaxf(bi.x, bj.x);
        float yy1 = fmaxf(bi.y, bj.y);
        float xx2 = fminf(bi.z, bj.z);
        float yy2 = fmaxf(bi.w, bj.w);   // reference bug: maximum, not minimum
        float w = fmaxf(0.f, xx2 - xx1 + 1.f);
        float h = fmaxf(0.f, yy2 - yy1 + 1.f);
        float inter = w * h;
        float den = ai + car[jt][jj] - inter;
        bool sup = (den > 0.f) ? (inter > 0.7f * den) : ((den == 0.f) && (inter > 0.f));
        word |= ((unsigned long long)sup) << jj;
    }
    g_maskT[(size_t)gj * ROWS + i] = word;   // coalesced across tt
}

// ---------------- greedy NMS scan + top-300 emit (fused, single barrier/cb) ----------------
// ms & s_remv double-buffered; greedy computed redundantly by ALL threads (identical
// result) so no second barrier / kept broadcast is needed. Kept words collected in
// smem; emit runs in the same block afterwards.
__global__ __launch_bounds__(256) void nms_scan_out_kernel(float* __restrict__ out) {
    __shared__ unsigned long long ms[2][64];
    __shared__ unsigned long long s_remvb[2];
    __shared__ unsigned long long s_keep[NW];
    __shared__ int cnts[256];
    __shared__ int offs[256];
    __shared__ int Ktot;
    int t = threadIdx.x;
    unsigned long long remv = 0;                       // thread t owns word g=t
    unsigned long long nextdiag = (t < 64) ? g_maskT[t] : 0ull;

    for (int cb = 0; cb < NW; cb++) {
        int buf = cb & 1;
        if (t < 64) ms[buf][t] = nextdiag;
        if (t == cb) s_remvb[buf] = remv;
        __syncthreads();
        if (t < 64 && cb + 1 < NW)
            nextdiag = g_maskT[(size_t)(cb + 1) * ROWS + (cb + 1) * 64 + t];
        // redundant greedy in every thread (identical result)
        unsigned long long v = s_remvb[buf], kept = 0ull;
        {
            int lim = PRE - cb * 64; if (lim > 64) lim = 64;
            unsigned long long avail = ~v;
            if (lim < 64) avail &= (1ull << lim) - 1ull;
            while (avail) {
                int j = __ffsll((long long)avail) - 1;
                kept |= 1ull << j;
                v |= ms[buf][j];
                avail &= ~v;
                avail &= (j < 63) ? (~0ull << (j + 1)) : 0ull;
            }
        }
        if (t == 0) s_keep[cb] = kept;
        if (t > cb && t < NW) {
            unsigned long long kk = kept;
            const unsigned long long* rowT = g_maskT + (size_t)t * ROWS + cb * 64;
            while (kk) {
                unsigned long long m[8];
#pragma unroll
                for (int u = 0; u < 8; u++) m[u] = 0ull;
#pragma unroll
                for (int u = 0; u < 8; u++) {
                    if (!kk) break;
                    int j = __ffsll((long long)kk) - 1; kk &= kk - 1;
                    m[u] = rowT[j];
                }
                remv |= ((m[0] | m[1]) | (m[2] | m[3])) |
                        ((m[4] | m[5]) | (m[6] | m[7]));
            }
        }
        // no second barrier: next iteration writes the OTHER buffer
    }
    __syncthreads();

    // ---- emit top-300 (kept in order, then non-kept by index) ----
    int lo = t * 24;
    int hi = lo + 24; if (hi > PRE) hi = PRE;
    int c = 0;
    for (int i = lo; i < hi; i++)
        c += (int)((s_keep[i >> 6] >> (i & 63)) & 1ull);
    cnts[t] = c;
    __syncthreads();
    if (t == 0) {
        int r = 0;
        for (int q = 0; q < 256; q++) { offs[q] = r; r += cnts[q]; }
        Ktot = r;
    }
    __syncthreads();
    int K = Ktot;
    int pk = offs[t];
    for (int i = lo; i < hi; i++) {
        bool kept = (s_keep[i >> 6] >> (i & 63)) & 1ull;
        int pos = kept ? pk : (K + (i - pk));
        if (kept) pk++;
        if (pos < POST) {
            float4 b = g_sbox[i];
            out[pos * 4 + 0] = b.x;
            out[pos * 4 + 1] = b.y;
            out[pos * 4 + 2] = b.z - b.x + 1.f;
            out[pos * 4 + 3] = b.w - b.y + 1.f;
        }
    }
}

// ---------------- launch ----------------
extern "C" void kernel_launch(void* const* d_in, const int* in_sizes, int n_in,
                              void* d_out, int out_size) {
    const float* in_features = (const float*)d_in[0];
    const float* conv_w = (const float*)d_in[1];
    const float* conv_b = (const float*)d_in[2];
    const float* reg_w  = (const float*)d_in[3];
    const float* reg_b  = (const float*)d_in[4];
    const float* cls_w  = (const float*)d_in[5];
    const float* cls_b  = (const float*)d_in[6];
    float* out = (float*)d_out;

    // only batch index 7 feeds the output
    const float* in7 = in_features + (size_t)7 * 512 * NPIX;

    cudaFuncSetAttribute(conv3_kernel,
                         cudaFuncAttributeMaxDynamicSharedMemorySize, DSMSZ);

    prep_w_kernel<<<512, 256>>>(conv_w);                         // 0
    prep_in_kernel<<<(OC * PADCH + 255) / 256, 256>>>(in7);      // 1
    setup_pad_kernel<<<1, 32>>>();                               // 2
    conv3_kernel<<<dim3(32, 4), 256, DSMSZ>>>(conv_b);           // 3 <- profiled
    heads_part_kernel<<<dim3(20, 8), 128>>>(reg_w, cls_w);       // 4
    heads_fin_kernel<<<40, 64>>>(reg_b, cls_b);                  // 5
    bucket_sum_kernel<<<256, 256>>>();                           // 6
    bucket_pref_kernel<<<256, 256>>>();                          // 7
    bucket_fill_kernel<<<88, 256>>>();                           // 8
    rank_scatter_kernel<<<88, 256>>>();                          // 9
    nms_mask_kernel<<<dim3(24, NW), 256>>>();                    // 10
    nms_scan_out_kernel<<<1, 256>>>(out);                        // 11
}